// round 1
// baseline (speedup 1.0000x reference)
#include <cuda_runtime.h>

// EfronLossPenalty: bucketized Efron Cox partial-likelihood loss.
// times in [0, 8192), N = 8.4M. Sum over ranks l within a tie block is
// permutation-invariant, so only per-bucket aggregates (d, ers, rss) matter.

#define NBINS 8192
#define NREP  64
#define MASK40 ((1ULL << 40) - 1ULL)

// Scratch (static __device__ — no allocation anywhere)
__device__ float              g_W[NREP * NBINS];   // sum of exp(lr) over NON-events, per replica
__device__ unsigned long long g_P[NREP * NBINS];   // events: (count << 40) | fixedpoint(sum exp(lr), 2^-16)
__device__ float g_risk[NBINS];   // total exp(lr) per bucket
__device__ float g_ers[NBINS];    // event exp(lr) sum per bucket
__device__ float g_rss[NBINS];    // suffix sum of g_risk
__device__ int   g_d[NBINS];      // event count per bucket
__device__ float g_elr;           // sum e*lr
__device__ float g_terms;         // sum of log terms
__device__ int   g_nev;           // total events

__device__ __forceinline__ float block_reduce_sum(float v) {
    __shared__ float s[32];
    int lane = threadIdx.x & 31;
    int wid  = threadIdx.x >> 5;
    #pragma unroll
    for (int o = 16; o > 0; o >>= 1) v += __shfl_down_sync(0xffffffffu, v, o);
    if (lane == 0) s[wid] = v;
    __syncthreads();
    int nw = (blockDim.x + 31) >> 5;
    v = (threadIdx.x < nw) ? s[threadIdx.x] : 0.0f;
    if (wid == 0) {
        #pragma unroll
        for (int o = 16; o > 0; o >>= 1) v += __shfl_down_sync(0xffffffffu, v, o);
    }
    return v;  // valid in thread 0
}

__global__ void k_zero() {
    int tid = blockIdx.x * blockDim.x + threadIdx.x;
    int stride = gridDim.x * blockDim.x;
    for (int i = tid; i < NREP * NBINS; i += stride) {
        g_W[i] = 0.0f;
        g_P[i] = 0ULL;
    }
    if (tid == 0) { g_elr = 0.0f; g_terms = 0.0f; g_nev = 0; }
}

__device__ __forceinline__ void accum_one(int t, int e, float x, unsigned rep, float& elr) {
    float w = __expf(x);
    if (e) {
        unsigned long long pk = (1ULL << 40) + (unsigned long long)(w * 65536.0f + 0.5f);
        atomicAdd(&g_P[rep * NBINS + t], pk);
        elr += x;
    } else {
        atomicAdd(&g_W[rep * NBINS + t], w);
    }
}

__global__ void k_accum(const int* __restrict__ times, const int* __restrict__ events,
                        const float* __restrict__ lr, int n) {
    int tid = blockIdx.x * blockDim.x + threadIdx.x;
    int stride = gridDim.x * blockDim.x;
    unsigned rep = ((unsigned)(tid >> 5)) & (NREP - 1);   // per-warp replica row

    const int4*   t4 = (const int4*)times;
    const int4*   e4 = (const int4*)events;
    const float4* l4 = (const float4*)lr;
    int n4 = n >> 2;

    float elr = 0.0f;
    for (int i = tid; i < n4; i += stride) {
        int4   tv = t4[i];
        int4   ev = e4[i];
        float4 lv = l4[i];
        accum_one(tv.x, ev.x, lv.x, rep, elr);
        accum_one(tv.y, ev.y, lv.y, rep, elr);
        accum_one(tv.z, ev.z, lv.z, rep, elr);
        accum_one(tv.w, ev.w, lv.w, rep, elr);
    }
    // tail (n not multiple of 4)
    int base = n4 << 2;
    int rem  = n - base;
    if (tid < rem) accum_one(times[base + tid], events[base + tid], lr[base + tid], rep, elr);

    float bsum = block_reduce_sum(elr);
    if (threadIdx.x == 0 && bsum != 0.0f) atomicAdd(&g_elr, bsum);
}

__global__ void k_reduce() {
    int t = blockIdx.x * blockDim.x + threadIdx.x;   // 8192 threads total
    if (t >= NBINS) return;
    float wsum = 0.0f;
    unsigned long long psum = 0ULL;
    #pragma unroll 8
    for (int r = 0; r < NREP; r++) {
        wsum += g_W[r * NBINS + t];
        psum += g_P[r * NBINS + t];
    }
    int   d   = (int)(psum >> 40);
    float ers = (float)(psum & MASK40) * (1.0f / 65536.0f);
    g_risk[t] = wsum + ers;
    g_ers[t]  = ers;
    g_d[t]    = d;
    if (d) atomicAdd(&g_nev, d);
}

// Suffix sum over 8192 bins: one block of 1024 threads, 8 elements each.
__global__ void k_scan() {
    __shared__ float s[1024];
    int tid = threadIdx.x;
    float v[8];
    float csum = 0.0f;
    #pragma unroll
    for (int k = 0; k < 8; k++) {
        int t = NBINS - 1 - (tid * 8 + k);   // reversed order
        v[k] = g_risk[t];
        csum += v[k];
    }
    s[tid] = csum;
    __syncthreads();
    // Hillis-Steele inclusive scan over chunk sums
    for (int off = 1; off < 1024; off <<= 1) {
        float add = (tid >= off) ? s[tid - off] : 0.0f;
        __syncthreads();
        s[tid] += add;
        __syncthreads();
    }
    float run = (tid > 0) ? s[tid - 1] : 0.0f;   // exclusive base
    #pragma unroll
    for (int k = 0; k < 8; k++) {
        run += v[k];
        g_rss[NBINS - 1 - (tid * 8 + k)] = run;  // inclusive suffix sum
    }
}

__global__ void k_terms() {
    float sum = 0.0f;
    for (int t = blockIdx.x; t < NBINS; t += gridDim.x) {
        int d = g_d[t];
        if (d == 0) continue;
        float rss = g_rss[t];
        if (d == 1) {
            if (threadIdx.x == 0) sum += __logf(rss + 1e-12f);
        } else {
            float step = g_ers[t] / (float)d;            // (1/d)*ers
            for (int l = threadIdx.x; l < d; l += blockDim.x)
                sum += __logf(fmaxf(rss - (float)l * step, 1e-12f));
        }
    }
    float bsum = block_reduce_sum(sum);
    if (threadIdx.x == 0 && bsum != 0.0f) atomicAdd(&g_terms, bsum);
}

__global__ void k_final(float* __restrict__ out, int out_n) {
    float ne = fmaxf((float)g_nev, 1.0f);
    float v  = (g_terms - g_elr) / ne;
    for (int i = threadIdx.x; i < out_n; i += blockDim.x) out[i] = v;
}

extern "C" void kernel_launch(void* const* d_in, const int* in_sizes, int n_in,
                              void* d_out, int out_size) {
    const int*   times  = (const int*)d_in[0];
    const int*   events = (const int*)d_in[1];
    const float* lr     = (const float*)d_in[2];
    float*       out    = (float*)d_out;
    int n = in_sizes[0];

    k_zero  <<<512, 256>>>();
    k_accum <<<1184, 256>>>(times, events, lr, n);
    k_reduce<<<NBINS / 256, 256>>>();
    k_scan  <<<1, 1024>>>();
    k_terms <<<296, 256>>>();
    k_final <<<1, 256>>>(out, out_size);
}

// round 2
// speedup vs baseline: 1.2172x; 1.2172x over previous
#include <cuda_runtime.h>

// EfronLossPenalty — bucketized Efron Cox loss.
// times in [0, 8192). Per-tie-block sum over ranks l is permutation-invariant:
// only per-bucket (d, ers, rss) matter. The per-block log-sum collapses to a
// Gamma-function ratio: sum_l log(rss - (l/d)*ers) = d*log(s) + lgamma(x+1) - lgamma(x-d+1).

#define NBINS 8192
#define NREP  32
#define MASK40 ((1ULL << 40) - 1ULL)

// Static scratch (no allocation anywhere)
__device__ float              g_W[NREP * NBINS];   // non-event exp(lr) sums, per replica
__device__ unsigned long long g_P[NREP * NBINS];   // events: (count<<40) | fix16(sum exp(lr))
__device__ float g_risk[NBINS];
__device__ float g_ers[NBINS];
__device__ float g_rss[NBINS];
__device__ int   g_d[NBINS];
__device__ float g_elr;
__device__ float g_terms;
__device__ int   g_nev;
__device__ unsigned g_done_r;   // completion counter, reduce kernel
__device__ unsigned g_done_t;   // completion counter, terms kernel

__device__ __forceinline__ float block_reduce_sum(float v) {
    __shared__ float s[32];
    int lane = threadIdx.x & 31;
    int wid  = threadIdx.x >> 5;
    #pragma unroll
    for (int o = 16; o > 0; o >>= 1) v += __shfl_down_sync(0xffffffffu, v, o);
    if (lane == 0) s[wid] = v;
    __syncthreads();
    int nw = (blockDim.x + 31) >> 5;
    v = (threadIdx.x < nw) ? s[threadIdx.x] : 0.0f;
    if (wid == 0) {
        #pragma unroll
        for (int o = 16; o > 0; o >>= 1) v += __shfl_down_sync(0xffffffffu, v, o);
    }
    return v;  // valid in thread 0
}

__global__ void k_zero() {
    int tid = blockIdx.x * blockDim.x + threadIdx.x;
    int stride = gridDim.x * blockDim.x;
    for (int i = tid; i < NREP * NBINS; i += stride) {
        g_W[i] = 0.0f;
        g_P[i] = 0ULL;
    }
    if (tid == 0) {
        g_elr = 0.0f; g_terms = 0.0f; g_nev = 0;
        g_done_r = 0u; g_done_t = 0u;
    }
}

__device__ __forceinline__ void accum_one(int t, int e, float x, unsigned rep, float& elr) {
    float w = __expf(x);
    if (e) {
        unsigned long long pk = (1ULL << 40) + (unsigned long long)(w * 65536.0f + 0.5f);
        atomicAdd(&g_P[rep * NBINS + t], pk);
        elr += x;
    } else {
        atomicAdd(&g_W[rep * NBINS + t], w);
    }
}

__global__ void k_accum(const int* __restrict__ times, const int* __restrict__ events,
                        const float* __restrict__ lr, int n) {
    int tid = blockIdx.x * blockDim.x + threadIdx.x;
    int stride = gridDim.x * blockDim.x;
    unsigned rep = ((unsigned)(tid >> 5)) & (NREP - 1);

    const int4*   t4 = (const int4*)times;
    const int4*   e4 = (const int4*)events;
    const float4* l4 = (const float4*)lr;
    int n4 = n >> 2;

    float elr = 0.0f;
    for (int i = tid; i < n4; i += stride) {
        int4   tv = t4[i];
        int4   ev = e4[i];
        float4 lv = l4[i];
        accum_one(tv.x, ev.x, lv.x, rep, elr);
        accum_one(tv.y, ev.y, lv.y, rep, elr);
        accum_one(tv.z, ev.z, lv.z, rep, elr);
        accum_one(tv.w, ev.w, lv.w, rep, elr);
    }
    int base = n4 << 2;
    int rem  = n - base;
    if (tid < rem) accum_one(times[base + tid], events[base + tid], lr[base + tid], rep, elr);

    float bsum = block_reduce_sum(elr);
    if (threadIdx.x == 0 && bsum != 0.0f) atomicAdd(&g_elr, bsum);
}

// 64 blocks x 128 threads: per-bucket reduce over replicas; last block does the
// 8192-bin suffix scan inline (threadfence + counter handoff).
__global__ void k_reduce_scan() {
    int t = blockIdx.x * blockDim.x + threadIdx.x;   // 0..8191
    float wsum = 0.0f;
    unsigned long long psum = 0ULL;
    #pragma unroll
    for (int r = 0; r < NREP; r++) {
        wsum += g_W[r * NBINS + t];
        psum += g_P[r * NBINS + t];
    }
    int   d   = (int)(psum >> 40);
    float ers = (float)(psum & MASK40) * (1.0f / 65536.0f);
    g_risk[t] = wsum + ers;
    g_ers[t]  = ers;
    g_d[t]    = d;
    if (d) atomicAdd(&g_nev, d);

    __threadfence();
    __shared__ bool s_last;
    __syncthreads();
    if (threadIdx.x == 0) {
        unsigned prev = atomicAdd(&g_done_r, 1u);
        s_last = (prev == gridDim.x - 1);
    }
    __syncthreads();
    if (!s_last) return;

    // ---- suffix scan (128 threads x 64 elements) ----
    __threadfence();
    const int PER = NBINS / 128;   // 64
    float v[PER];
    float csum = 0.0f;
    int j = threadIdx.x;
    #pragma unroll
    for (int k = 0; k < PER; k++) {
        v[k] = __ldcg(&g_risk[NBINS - 1 - (j * PER + k)]);
        csum += v[k];
    }
    __shared__ float s[128];
    s[j] = csum;
    __syncthreads();
    for (int off = 1; off < 128; off <<= 1) {
        float add = (j >= off) ? s[j - off] : 0.0f;
        __syncthreads();
        s[j] += add;
        __syncthreads();
    }
    float run = (j > 0) ? s[j - 1] : 0.0f;
    #pragma unroll
    for (int k = 0; k < PER; k++) {
        run += v[k];
        g_rss[NBINS - 1 - (j * PER + k)] = run;
    }
}

// 64 blocks x 128 threads: one bucket per thread via Gamma identity;
// last block writes the final scalar.
__global__ void k_terms_final(float* __restrict__ out, int out_n) {
    int t = blockIdx.x * blockDim.x + threadIdx.x;   // 0..8191
    float term = 0.0f;
    int d = g_d[t];
    if (d > 0) {
        float rss = g_rss[t];
        float ers = g_ers[t];
        if (d == 1) {
            term = __logf(rss + 1e-12f);
        } else {
            double s = (double)ers / (double)d;
            double x = (double)rss / s;
            if (x - (double)(d - 1) > 0.5) {
                // sum_l log(rss - l*s) = d*log(s) + lgamma(x+1) - lgamma(x-d+1)
                term = (float)((double)d * log(s) + lgamma(x + 1.0) - lgamma(x - (double)d + 1.0));
            } else {
                // near-clamp fallback (matches reference's per-term max(.,eps))
                float step = ers / (float)d;
                float sum = 0.0f;
                for (int l = 0; l < d; l++)
                    sum += __logf(fmaxf(rss - (float)l * step, 1e-12f));
                term = sum;
            }
        }
    }
    float bsum = block_reduce_sum(term);
    if (threadIdx.x == 0 && bsum != 0.0f) atomicAdd(&g_terms, bsum);

    __threadfence();
    __shared__ bool s_last;
    __syncthreads();
    if (threadIdx.x == 0) {
        unsigned prev = atomicAdd(&g_done_t, 1u);
        s_last = (prev == gridDim.x - 1);
    }
    __syncthreads();
    if (!s_last) return;

    __threadfence();
    float terms = atomicAdd(&g_terms, 0.0f);   // coherent read
    float elr   = atomicAdd(&g_elr, 0.0f);
    int   nev   = atomicAdd(&g_nev, 0);
    float ne = fmaxf((float)nev, 1.0f);
    float val = (terms - elr) / ne;
    for (int i = threadIdx.x; i < out_n; i += blockDim.x) out[i] = val;
}

extern "C" void kernel_launch(void* const* d_in, const int* in_sizes, int n_in,
                              void* d_out, int out_size) {
    const int*   times  = (const int*)d_in[0];
    const int*   events = (const int*)d_in[1];
    const float* lr     = (const float*)d_in[2];
    float*       out    = (float*)d_out;
    int n = in_sizes[0];

    k_zero        <<<512, 256>>>();
    k_accum       <<<1184, 256>>>(times, events, lr, n);
    k_reduce_scan <<<64, 128>>>();
    k_terms_final <<<64, 128>>>(out, out_size);
}

// round 3
// speedup vs baseline: 1.3229x; 1.0868x over previous
#include <cuda_runtime.h>

// EfronLossPenalty — bucketized Efron Cox loss, times in [0, 8192).
// Per-tie-block rank sum is permutation-invariant -> only (d, ers, rss) per
// bucket matter. Block log-sum collapses via falling factorial:
//   sum_{l=0}^{d-1} log(rss - l*s) = d*log(s) + lgamma(x+1) - lgamma(x-d+1),
// with s = ers/d, x = rss/s.

#define NBINS 8192
#define NREP  16
#define MASK40 ((1ULL << 40) - 1ULL)
#define POST_BLOCKS 64
#define POST_THREADS 128

// Static scratch. Zero-initialized at module load; every launch restores the
// all-zero invariant before exiting, so no separate zeroing kernel is needed.
__device__ float              g_W[NREP * NBINS];   // non-event exp(lr) sums
__device__ unsigned long long g_P[NREP * NBINS];   // (count<<40) | fix16(event exp(lr) sum)
__device__ float g_chunk[POST_BLOCKS];
__device__ float g_elr;
__device__ float g_terms;
__device__ float g_nev;
__device__ unsigned g_done1;
__device__ unsigned g_done2;

__device__ __forceinline__ float block_reduce_sum(float v) {
    __shared__ float s[32];
    int lane = threadIdx.x & 31;
    int wid  = threadIdx.x >> 5;
    #pragma unroll
    for (int o = 16; o > 0; o >>= 1) v += __shfl_down_sync(0xffffffffu, v, o);
    if (lane == 0) s[wid] = v;
    __syncthreads();
    int nw = (blockDim.x + 31) >> 5;
    v = (threadIdx.x < nw) ? s[threadIdx.x] : 0.0f;
    if (wid == 0) {
        #pragma unroll
        for (int o = 16; o > 0; o >>= 1) v += __shfl_down_sync(0xffffffffu, v, o);
    }
    __syncthreads();   // protect s[] against immediate reuse
    return v;          // valid in thread 0
}

// Stirling lgamma: shift z up to >= 8, then 3-term asymptotic series.
// abs err ~3e-8 for z>=8 — far inside the 1e-3 harness tolerance.
__device__ __forceinline__ double lgam(double z) {
    double shift = 1.0;
    while (z < 8.0) { shift *= z; z += 1.0; }
    double r = 1.0 / z, r2 = r * r;
    double ser = r * (8.3333333333333333e-2 +
                 r2 * (-2.7777777777777778e-3 +
                 r2 * 7.9365079365079365e-4));
    return (z - 0.5) * log(z) - z + 0.918938533204672742 + ser - log(shift);
}

__device__ __forceinline__ void accum_one(int t, int e, float x, unsigned rep, float& elr) {
    float w = __expf(x);
    if (e) {
        unsigned long long pk = (1ULL << 40) + (unsigned long long)(w * 65536.0f + 0.5f);
        atomicAdd(&g_P[rep * NBINS + t], pk);
        elr += x;
    } else {
        atomicAdd(&g_W[rep * NBINS + t], w);
    }
}

__global__ void k_accum(const int* __restrict__ times, const int* __restrict__ events,
                        const float* __restrict__ lr, int n) {
    int tid = blockIdx.x * blockDim.x + threadIdx.x;
    int stride = gridDim.x * blockDim.x;
    unsigned rep = ((unsigned)(tid >> 5)) & (NREP - 1);   // per-warp replica row

    const int4*   t4 = (const int4*)times;
    const int4*   e4 = (const int4*)events;
    const float4* l4 = (const float4*)lr;
    int n4 = n >> 2;

    float elr = 0.0f;
    for (int i = tid; i < n4; i += stride) {
        int4   tv = t4[i];
        int4   ev = e4[i];
        float4 lv = l4[i];
        accum_one(tv.x, ev.x, lv.x, rep, elr);
        accum_one(tv.y, ev.y, lv.y, rep, elr);
        accum_one(tv.z, ev.z, lv.z, rep, elr);
        accum_one(tv.w, ev.w, lv.w, rep, elr);
    }
    int base = n4 << 2;
    int rem  = n - base;
    if (tid < rem) accum_one(times[base + tid], events[base + tid], lr[base + tid], rep, elr);

    float bsum = block_reduce_sum(elr);
    if (threadIdx.x == 0 && bsum != 0.0f) atomicAdd(&g_elr, bsum);
}

// One fused kernel: replica reduce (+ re-zero), cross-block suffix scan,
// per-bucket Efron terms via Stirling, final scalar. 64 blocks x 128 threads,
// one bucket per thread; all blocks resident -> spin phases are safe.
__global__ void k_post(float* __restrict__ out, int out_n) {
    int b = blockIdx.x * POST_THREADS + threadIdx.x;   // bucket 0..8191

    // --- phase 1: reduce over replicas, restore zeros ---
    float wsum = 0.0f;
    unsigned long long psum = 0ULL;
    #pragma unroll
    for (int r = 0; r < NREP; r++) {
        int idx = r * NBINS + b;
        wsum += g_W[idx]; g_W[idx] = 0.0f;
        psum += g_P[idx]; g_P[idx] = 0ULL;
    }
    int   d    = (int)(psum >> 40);
    float ers  = (float)(psum & MASK40) * (1.0f / 65536.0f);
    float risk = wsum + ers;

    // --- phase 2: cross-block suffix scan of risk ---
    float csum = block_reduce_sum(risk);
    if (threadIdx.x == 0) {
        g_chunk[blockIdx.x] = csum;
        __threadfence();
        atomicAdd(&g_done1, 1u);
        while (*((volatile unsigned*)&g_done1) < gridDim.x) { }
    }
    __syncthreads();
    __threadfence();

    float suffix_base = 0.0f;
    for (int j = blockIdx.x + 1; j < POST_BLOCKS; j++) suffix_base += g_chunk[j];

    __shared__ float sv[POST_THREADS];
    sv[threadIdx.x] = risk;
    __syncthreads();
    for (int off = 1; off < POST_THREADS; off <<= 1) {
        float add = (threadIdx.x + off < POST_THREADS) ? sv[threadIdx.x + off] : 0.0f;
        __syncthreads();
        sv[threadIdx.x] += add;
        __syncthreads();
    }
    float rss = suffix_base + sv[threadIdx.x];   // inclusive suffix sum at bucket b

    // --- phase 3: Efron terms ---
    float term = 0.0f;
    if (d == 1) {
        term = __logf(rss + 1e-12f);
    } else if (d > 1) {
        double s  = (double)ers / (double)d;
        double x  = (double)rss / s;
        double zl = x - (double)d + 1.0;
        if (zl > 0.5) {
            term = (float)((double)d * log(s) + lgam(x + 1.0) - lgam(zl));
        } else {   // near-clamp fallback, matches reference per-term max(.,eps)
            float step = ers / (float)d;
            float sum = 0.0f;
            for (int l = 0; l < d; l++)
                sum += __logf(fmaxf(rss - (float)l * step, 1e-12f));
            term = sum;
        }
    }
    float tsum = block_reduce_sum(term);
    if (threadIdx.x == 0 && tsum != 0.0f) atomicAdd(&g_terms, tsum);
    float dsum = block_reduce_sum((float)d);
    if (threadIdx.x == 0 && dsum != 0.0f) atomicAdd(&g_nev, dsum);

    // --- phase 4: last block finalizes and resets scalars ---
    __threadfence();
    __shared__ bool s_last;
    __syncthreads();
    if (threadIdx.x == 0) {
        unsigned prev = atomicAdd(&g_done2, 1u);
        s_last = (prev == gridDim.x - 1);
    }
    __syncthreads();
    if (!s_last) return;

    __threadfence();
    float terms = *((volatile float*)&g_terms);
    float elr   = *((volatile float*)&g_elr);
    float nev   = *((volatile float*)&g_nev);
    float val   = (terms - elr) / fmaxf(nev, 1.0f);
    for (int i = threadIdx.x; i < out_n; i += POST_THREADS) out[i] = val;

    if (threadIdx.x == 0) {   // restore all-zero invariant for next replay
        g_elr = 0.0f; g_terms = 0.0f; g_nev = 0.0f;
        g_done1 = 0u; g_done2 = 0u;
    }
}

extern "C" void kernel_launch(void* const* d_in, const int* in_sizes, int n_in,
                              void* d_out, int out_size) {
    const int*   times  = (const int*)d_in[0];
    const int*   events = (const int*)d_in[1];
    const float* lr     = (const float*)d_in[2];
    float*       out    = (float*)d_out;
    int n = in_sizes[0];

    k_accum<<<1184, 256>>>(times, events, lr, n);
    k_post <<<POST_BLOCKS, POST_THREADS>>>(out, out_size);
}

// round 4
// speedup vs baseline: 1.4930x; 1.1286x over previous
#include <cuda_runtime.h>

// EfronLossPenalty — bucketized Efron Cox loss, times in [0, 8192).
// Per-tie-block rank sum is permutation-invariant -> only (d, ers, rss) per
// bucket matter. Block log-sum collapses via falling factorial:
//   sum_{l=0}^{d-1} log(rss - l*s) = d*log(s) + lgamma(x+1) - lgamma(x-d+1),
// s = ers/d, x = rss/s — evaluated via a cancellation-free float Stirling diff.
//
// Accumulation: ONE packed 64-bit atomic per element into g_P[rep][bin]:
//   bits [52:64) = event count, [26:52) = fix10 event-risk sum, [0:26) = fix10 total-risk sum.
// Branch-free (events add to all fields, non-events only to the low field).

#define NBINS 8192
#define NREP  16
#define MASK26 ((1ULL << 26) - 1ULL)
#define FIX 1024.0f
#define POST_BLOCKS 64
#define POST_THREADS 128

// Static scratch. Zero-initialized at module load; every launch restores the
// all-zero invariant before exiting (graph-replay safe, no zeroing kernel).
__device__ unsigned long long g_P[NREP * NBINS];
__device__ float g_chunk[POST_BLOCKS];
__device__ float g_elr;
__device__ float g_terms;
__device__ float g_nev;
__device__ unsigned g_done1;
__device__ unsigned g_done2;

__device__ __forceinline__ float block_reduce_sum(float v) {
    __shared__ float s[32];
    int lane = threadIdx.x & 31;
    int wid  = threadIdx.x >> 5;
    #pragma unroll
    for (int o = 16; o > 0; o >>= 1) v += __shfl_down_sync(0xffffffffu, v, o);
    if (lane == 0) s[wid] = v;
    __syncthreads();
    int nw = (blockDim.x + 31) >> 5;
    v = (threadIdx.x < nw) ? s[threadIdx.x] : 0.0f;
    if (wid == 0) {
        #pragma unroll
        for (int o = 16; o > 0; o >>= 1) v += __shfl_down_sync(0xffffffffu, v, o);
    }
    __syncthreads();   // protect s[] against reuse
    return v;          // valid in thread 0
}

__device__ __forceinline__ void accum_one(int t, int e, float x, unsigned rep, float& elr) {
    float w = __expf(x);
    unsigned wi = (unsigned)(w * FIX + 0.5f);
    unsigned long long pk = (unsigned long long)wi
                          + ((unsigned long long)(wi * (unsigned)e) << 26)
                          + ((unsigned long long)(unsigned)e << 52);
    atomicAdd(&g_P[rep * NBINS + t], pk);
    elr += e ? x : 0.0f;
}

__global__ void __launch_bounds__(256) k_accum(
        const int* __restrict__ times, const int* __restrict__ events,
        const float* __restrict__ lr, int n) {
    int tid = blockIdx.x * blockDim.x + threadIdx.x;
    int stride = gridDim.x * blockDim.x;
    unsigned rep = ((unsigned)(tid >> 5)) & (NREP - 1);   // per-warp replica row

    const int4*   t4 = (const int4*)times;
    const int4*   e4 = (const int4*)events;
    const float4* l4 = (const float4*)lr;
    int n4 = n >> 2;

    float elr = 0.0f;
    for (int i = tid; i < n4; i += stride) {
        int4   tv = t4[i];
        int4   ev = e4[i];
        float4 lv = l4[i];
        accum_one(tv.x, ev.x, lv.x, rep, elr);
        accum_one(tv.y, ev.y, lv.y, rep, elr);
        accum_one(tv.z, ev.z, lv.z, rep, elr);
        accum_one(tv.w, ev.w, lv.w, rep, elr);
    }
    int base = n4 << 2;
    int rem  = n - base;
    if (tid < rem) accum_one(times[base + tid], events[base + tid], lr[base + tid], rep, elr);

    float bsum = block_reduce_sum(elr);
    if (threadIdx.x == 0 && bsum != 0.0f) atomicAdd(&g_elr, bsum);
}

// Fused post-pass: replica reduce (+ re-zero), cross-block suffix scan,
// per-bucket Efron terms (float Stirling), final scalar.
// 64 blocks x 128 threads, one bucket per thread; all blocks resident.
__global__ void __launch_bounds__(POST_THREADS) k_post(float* __restrict__ out, int out_n) {
    int b = blockIdx.x * POST_THREADS + threadIdx.x;   // bucket 0..8191

    // --- phase 1: reduce over replicas, restore zeros ---
    unsigned long long psum = 0ULL;
    #pragma unroll
    for (int r = 0; r < NREP; r++) {
        int idx = r * NBINS + b;
        psum += g_P[idx];
        g_P[idx] = 0ULL;
    }
    int   d    = (int)(psum >> 52);
    float ers  = (float)((psum >> 26) & MASK26) * (1.0f / FIX);
    float risk = (float)(psum & MASK26) * (1.0f / FIX);

    // --- phase 2: cross-block suffix scan of risk ---
    float csum = block_reduce_sum(risk);
    if (threadIdx.x == 0) {
        g_chunk[blockIdx.x] = csum;
        __threadfence();
        atomicAdd(&g_done1, 1u);
        while (*((volatile unsigned*)&g_done1) < gridDim.x) { }
    }
    __syncthreads();
    __threadfence();

    float suffix_base = 0.0f;
    for (int j = blockIdx.x + 1; j < POST_BLOCKS; j++) suffix_base += g_chunk[j];

    __shared__ float sv[POST_THREADS];
    sv[threadIdx.x] = risk;
    __syncthreads();
    for (int off = 1; off < POST_THREADS; off <<= 1) {
        float add = (threadIdx.x + off < POST_THREADS) ? sv[threadIdx.x + off] : 0.0f;
        __syncthreads();
        sv[threadIdx.x] += add;
        __syncthreads();
    }
    float rss = suffix_base + sv[threadIdx.x];   // inclusive suffix sum at bucket b

    // --- phase 3: Efron terms (all-float, cancellation-free) ---
    float term = 0.0f;
    if (d == 1) {
        term = logf(rss + 1e-12f);
    } else if (d > 1) {
        float s  = ers / (float)d;
        float x  = rss / s;
        float a  = x + 1.0f;
        float bb = x - (float)d + 1.0f;
        if (bb > 0.5f) {
            // F(z) = (z-1/2)ln z - z + 1/(12z);  F(a)-F(b) rearranged:
            //   = d*L + (m-1/2)*log1p(d/b) - d + (1/a - 1/b)/12,  L=(ln a+ln b)/2
            float la = logf(a), lb = logf(bb);
            float L  = 0.5f * (la + lb);
            float m  = 0.5f * (a + bb);
            float dlt = log1pf((float)d / bb);
            term = (float)d * (logf(s) + L - 1.0f)
                 + (m - 0.5f) * dlt
                 + (1.0f / 12.0f) * (1.0f / a - 1.0f / bb);
        } else {   // near-clamp fallback (matches reference per-term max(.,eps))
            float sum = 0.0f;
            for (int l = 0; l < d; l++)
                sum += __logf(fmaxf(rss - (float)l * s, 1e-12f));
            term = sum;
        }
    }
    float tsum = block_reduce_sum(term);
    if (threadIdx.x == 0 && tsum != 0.0f) atomicAdd(&g_terms, tsum);
    float dsum = block_reduce_sum((float)d);
    if (threadIdx.x == 0 && dsum != 0.0f) atomicAdd(&g_nev, dsum);

    // --- phase 4: last block finalizes and resets scalars ---
    __threadfence();
    __shared__ bool s_last;
    __syncthreads();
    if (threadIdx.x == 0) {
        unsigned prev = atomicAdd(&g_done2, 1u);
        s_last = (prev == gridDim.x - 1);
    }
    __syncthreads();
    if (!s_last) return;

    __threadfence();
    float terms = *((volatile float*)&g_terms);
    float elr   = *((volatile float*)&g_elr);
    float nev   = *((volatile float*)&g_nev);
    float val   = (terms - elr) / fmaxf(nev, 1.0f);
    for (int i = threadIdx.x; i < out_n; i += POST_THREADS) out[i] = val;

    if (threadIdx.x == 0) {   // restore all-zero invariant for next replay
        g_elr = 0.0f; g_terms = 0.0f; g_nev = 0.0f;
        g_done1 = 0u; g_done2 = 0u;
    }
}

extern "C" void kernel_launch(void* const* d_in, const int* in_sizes, int n_in,
                              void* d_out, int out_size) {
    const int*   times  = (const int*)d_in[0];
    const int*   events = (const int*)d_in[1];
    const float* lr     = (const float*)d_in[2];
    float*       out    = (float*)d_out;
    int n = in_sizes[0];

    k_accum<<<1184, 256>>>(times, events, lr, n);
    k_post <<<POST_BLOCKS, POST_THREADS>>>(out, out_size);
}